// round 1
// baseline (speedup 1.0000x reference)
#include <cuda_runtime.h>

#define BB 64
#define LL 512
#define HH 512

// Scratch (device globals — no allocation allowed)
__device__ float g_S[4][HH][BB];    // [sum][h][b]   (b-fast for coalesced stage-2 reads)
__device__ float g_Wt[4][HH][HH];   // transposed weights: [w][h][k]; 0=th_u,1=th_l,2=sh_u,3=sh_l
__device__ float g_U[HH][BB];       // [k][b]
__device__ float g_V[HH][BB];
__device__ float g_LV[BB][HH];      // loc_vec [b][k]
__device__ float g_usr[HH];

// ---------------------------------------------------------------------------
__global__ void k_zero() {
    int i = blockIdx.x * blockDim.x + threadIdx.x;
    float4 z = make_float4(0.f, 0.f, 0.f, 0.f);
    if (i < 4 * HH * BB / 4) reinterpret_cast<float4*>(g_S)[i] = z;
    if (i < HH * BB / 4) {
        reinterpret_cast<float4*>(g_U)[i]  = z;
        reinterpret_cast<float4*>(g_V)[i]  = z;
        reinterpret_cast<float4*>(g_LV)[i] = z;
    }
}

// ---------------------------------------------------------------------------
// Transpose 4 HxH weights into h-major layout g_Wt[w][h][k] = W[w][k][h]
__global__ void k_transpose(const float* __restrict__ w0, const float* __restrict__ w1,
                            const float* __restrict__ w2, const float* __restrict__ w3) {
    __shared__ float tile[32][33];
    int w = blockIdx.z;
    const float* W = (w == 0) ? w0 : (w == 1) ? w1 : (w == 2) ? w2 : w3;
    int kk = blockIdx.x * 32;
    int hh = blockIdx.y * 32;
    #pragma unroll
    for (int i = threadIdx.y; i < 32; i += 8)
        tile[i][threadIdx.x] = W[(size_t)(kk + i) * HH + hh + threadIdx.x];
    __syncthreads();
    #pragma unroll
    for (int i = threadIdx.y; i < 32; i += 8)
        g_Wt[w][hh + i][kk + threadIdx.x] = tile[threadIdx.x][i];
}

// ---------------------------------------------------------------------------
// usr_vec[k] = sum_h Wih[k][h] * h0[h]
__global__ void k_usr(const float* __restrict__ wih, const float* __restrict__ h0) {
    int k    = blockIdx.x * 16 + (threadIdx.x >> 4);
    int lane = threadIdx.x & 15;
    float s = 0.f;
    #pragma unroll 8
    for (int h = lane; h < HH; h += 16)
        s += wih[(size_t)k * HH + h] * __ldg(&h0[h]);
    #pragma unroll
    for (int o = 8; o; o >>= 1) s += __shfl_down_sync(0xffffffffu, s, o, 16);
    if (lane == 0) g_usr[k] = s;
}

// ---------------------------------------------------------------------------
// Masked gather-accumulate of 4 weighted sums over l:
//   S1 += (c*a)*loc, S2 += (c*b)*loc, S3 += (d*a)*loc, S4 += (d*b)*loc
// Grid: (b, split of 4).  Block: 512 threads, thread = h.
__global__ void k_gather(const float* __restrict__ tdu, const float* __restrict__ tdl,
                         const float* __restrict__ ldu, const float* __restrict__ ldl,
                         const int*   __restrict__ cur, const int* __restrict__ llen,
                         const float* __restrict__ locw) {
    int b = blockIdx.x;
    int split = blockIdx.y;                 // 0..3
    int len = llen[b];
    int h = threadIdx.x;

    __shared__ float s_ca[128], s_cb[128], s_da[128], s_db[128];
    __shared__ int   s_idx[128];

    if (h < 128) {
        int l = split + 4 * h;
        if (l < len) {
            int o = b * LL + l;
            float tu = tdu[o], tl = tdl[o];
            float lu = ldu[o], ll = ldl[o];
            float tden = 1.f / (tu + tl + 1e-9f);
            float lden = 1.f / (lu + ll + 1e-9f);
            float a = tu * tden, bb_ = tl * tden;
            float c = lu * lden, dd  = ll * lden;
            s_ca[h] = c * a;  s_cb[h] = c * bb_;
            s_da[h] = dd * a; s_db[h] = dd * bb_;
            s_idx[h] = cur[o];
        }
    }
    __syncthreads();

    int cnt = (len > split) ? ((len - split + 3) >> 2) : 0;

    float a1 = 0.f, a2 = 0.f, a3 = 0.f, a4 = 0.f;
    #pragma unroll 4
    for (int i = 0; i < cnt; ++i) {
        float v = __ldg(&locw[(size_t)s_idx[i] * HH + h]);
        a1 += s_ca[i] * v;
        a2 += s_cb[i] * v;
        a3 += s_da[i] * v;
        a4 += s_db[i] * v;
    }
    if (cnt > 0) {
        atomicAdd(&g_S[0][h][b], a1);
        atomicAdd(&g_S[1][h][b], a2);
        atomicAdd(&g_S[2][h][b], a3);
        atomicAdd(&g_S[3][h][b], a4);
    }
}

// ---------------------------------------------------------------------------
// U[b][k] = sum_h Wtu[k][h]*S1[b][h] + Wtl[k][h]*S2[b][h]   (stored g_U[k][b])
// V[b][k] = sum_h Wtu[k][h]*S3[b][h] + Wtl[k][h]*S4[b][h]
// Grid (16 k-blocks of 32, 8 h-splits of 64). Block 256 = 8 warps;
// warp owns 4 consecutive k, lane owns a b-pair (float2).
__global__ void k_mm1() {
    int warp = threadIdx.x >> 5, lane = threadIdx.x & 31;
    int k0 = blockIdx.x * 32 + warp * 4;
    int h0 = blockIdx.y * 64;

    float aU[4][2] = {{0.f}}, aV[4][2] = {{0.f}};
    #pragma unroll 2
    for (int h = h0; h < h0 + 64; ++h) {
        float2 s1 = *reinterpret_cast<const float2*>(&g_S[0][h][2 * lane]);
        float2 s2 = *reinterpret_cast<const float2*>(&g_S[1][h][2 * lane]);
        float2 s3 = *reinterpret_cast<const float2*>(&g_S[2][h][2 * lane]);
        float2 s4 = *reinterpret_cast<const float2*>(&g_S[3][h][2 * lane]);
        float4 wu = *reinterpret_cast<const float4*>(&g_Wt[0][h][k0]);
        float4 wl = *reinterpret_cast<const float4*>(&g_Wt[1][h][k0]);
        float wuj[4] = {wu.x, wu.y, wu.z, wu.w};
        float wlj[4] = {wl.x, wl.y, wl.z, wl.w};
        #pragma unroll
        for (int j = 0; j < 4; ++j) {
            aU[j][0] += wuj[j] * s1.x + wlj[j] * s2.x;
            aU[j][1] += wuj[j] * s1.y + wlj[j] * s2.y;
            aV[j][0] += wuj[j] * s3.x + wlj[j] * s4.x;
            aV[j][1] += wuj[j] * s3.y + wlj[j] * s4.y;
        }
    }
    #pragma unroll
    for (int j = 0; j < 4; ++j) {
        atomicAdd(&g_U[k0 + j][2 * lane],     aU[j][0]);
        atomicAdd(&g_U[k0 + j][2 * lane + 1], aU[j][1]);
        atomicAdd(&g_V[k0 + j][2 * lane],     aV[j][0]);
        atomicAdd(&g_V[k0 + j][2 * lane + 1], aV[j][1]);
    }
}

// ---------------------------------------------------------------------------
// loc_vec[b][k] = sum_h Wsu[k][h]*U[b][h] + Wsl[k][h]*V[b][h]
__global__ void k_mm2() {
    int warp = threadIdx.x >> 5, lane = threadIdx.x & 31;
    int k0 = blockIdx.x * 32 + warp * 4;
    int h0 = blockIdx.y * 64;

    float acc[4][2] = {{0.f}};
    #pragma unroll 2
    for (int h = h0; h < h0 + 64; ++h) {
        float2 u = *reinterpret_cast<const float2*>(&g_U[h][2 * lane]);
        float2 v = *reinterpret_cast<const float2*>(&g_V[h][2 * lane]);
        float4 wu = *reinterpret_cast<const float4*>(&g_Wt[2][h][k0]);
        float4 wl = *reinterpret_cast<const float4*>(&g_Wt[3][h][k0]);
        float wuj[4] = {wu.x, wu.y, wu.z, wu.w};
        float wlj[4] = {wl.x, wl.y, wl.z, wl.w};
        #pragma unroll
        for (int j = 0; j < 4; ++j) {
            acc[j][0] += wuj[j] * u.x + wlj[j] * v.x;
            acc[j][1] += wuj[j] * u.y + wlj[j] * v.y;
        }
    }
    #pragma unroll
    for (int j = 0; j < 4; ++j) {
        atomicAdd(&g_LV[2 * lane][k0 + j],     acc[j][0]);
        atomicAdd(&g_LV[2 * lane + 1][k0 + j], acc[j][1]);
    }
}

// ---------------------------------------------------------------------------
// out[b][k] = softmax_k( loc_vec[b][k] + usr[k] )
__global__ void k_softmax(float* __restrict__ out) {
    int b = blockIdx.x;
    int t = threadIdx.x;        // 256 threads, 2 elements each
    int warp = t >> 5, lane = t & 31;
    __shared__ float sm[8];
    __shared__ float sbc;

    float x0 = g_LV[b][t]       + g_usr[t];
    float x1 = g_LV[b][t + 256] + g_usr[t + 256];

    float m = fmaxf(x0, x1);
    #pragma unroll
    for (int o = 16; o; o >>= 1) m = fmaxf(m, __shfl_xor_sync(0xffffffffu, m, o));
    if (lane == 0) sm[warp] = m;
    __syncthreads();
    if (t == 0) {
        float M = sm[0];
        #pragma unroll
        for (int i = 1; i < 8; ++i) M = fmaxf(M, sm[i]);
        sbc = M;
    }
    __syncthreads();
    float M = sbc;

    float e0 = expf(x0 - M), e1 = expf(x1 - M);
    float s = e0 + e1;
    #pragma unroll
    for (int o = 16; o; o >>= 1) s += __shfl_xor_sync(0xffffffffu, s, o);
    __syncthreads();           // all reads of sbc(M) done before reuse
    if (lane == 0) sm[warp] = s;
    __syncthreads();
    if (t == 0) {
        float S = 0.f;
        #pragma unroll
        for (int i = 0; i < 8; ++i) S += sm[i];
        sbc = S;
    }
    __syncthreads();
    float inv = 1.f / sbc;
    out[b * HH + t]       = e0 * inv;
    out[b * HH + t + 256] = e1 * inv;
}

// ---------------------------------------------------------------------------
extern "C" void kernel_launch(void* const* d_in, const int* in_sizes, int n_in,
                              void* d_out, int out_size) {
    const float* tdu  = (const float*)d_in[0];
    const float* tdl  = (const float*)d_in[1];
    const float* ldu  = (const float*)d_in[2];
    const float* ldl  = (const float*)d_in[3];
    const int*   cur  = (const int*)  d_in[4];
    const int*   llen = (const int*)  d_in[5];
    const float* wih  = (const float*)d_in[6];
    const float* wtu  = (const float*)d_in[7];
    const float* wtl  = (const float*)d_in[8];
    const float* wsu  = (const float*)d_in[9];
    const float* wsl  = (const float*)d_in[10];
    const float* h0   = (const float*)d_in[11];
    const float* locw = (const float*)d_in[12];
    float* out = (float*)d_out;

    k_zero<<<128, 256>>>();
    k_transpose<<<dim3(16, 16, 4), dim3(32, 8)>>>(wtu, wtl, wsu, wsl);
    k_usr<<<32, 256>>>(wih, h0);
    k_gather<<<dim3(64, 4), 512>>>(tdu, tdl, ldu, ldl, cur, llen, locw);
    k_mm1<<<dim3(16, 8), 256>>>();
    k_mm2<<<dim3(16, 8), 256>>>();
    k_softmax<<<64, 256>>>(out);
}

// round 2
// speedup vs baseline: 1.6445x; 1.6445x over previous
#include <cuda_runtime.h>

#define BB 64
#define LL 512
#define HH 512

// Scratch (device globals — no allocation allowed)
__device__ float g_S[HH][BB][4];    // 4 packed sums per (h,b): {ca,cb,da,db}-weighted
__device__ float g_Wt[4][HH][HH];   // transposed weights [w][h][k]; 0=th_u,1=th_l,2=sh_u,3=sh_l
__device__ float g_UV[HH][BB][2];   // packed {U,V} per (k,b)
__device__ float g_LV[BB][HH];      // loc_vec
__device__ float g_usr[HH];

// ---------------------------------------------------------------------------
// Fused pre-pass: blocks [0,1024) transpose weights, [1024,1152) zero scratch,
// [1152,1184) compute usr_vec = Wih @ h0.
__global__ void __launch_bounds__(256) k_pre(
        const float* __restrict__ w0, const float* __restrict__ w1,
        const float* __restrict__ w2, const float* __restrict__ w3,
        const float* __restrict__ wih, const float* __restrict__ h0) {
    int blk = blockIdx.x;
    int t = threadIdx.x;

    if (blk < 1024) {
        // transpose: 4 weights x 256 tiles of 32x32
        __shared__ float tile[32][33];
        int w = blk >> 8;
        int rem = blk & 255;
        int kk = (rem & 15) * 32;
        int hh = (rem >> 4) * 32;
        const float* W = (w == 0) ? w0 : (w == 1) ? w1 : (w == 2) ? w2 : w3;
        int tx = t & 31, ty = t >> 5;
        #pragma unroll
        for (int i = ty; i < 32; i += 8)
            tile[i][tx] = W[(size_t)(kk + i) * HH + hh + tx];
        __syncthreads();
        #pragma unroll
        for (int i = ty; i < 32; i += 8)
            g_Wt[w][hh + i][kk + tx] = tile[tx][i];
    } else if (blk < 1152) {
        // zero g_S (32768 f4) + g_UV (16384 f4) + g_LV (8192 f4) = 57344 float4
        int idx = (blk - 1024) * 256 + t;           // 32768 threads
        float4 z = make_float4(0.f, 0.f, 0.f, 0.f);
        #pragma unroll
        for (int i = idx; i < 57344; i += 32768) {
            if (i < 32768)       reinterpret_cast<float4*>(g_S)[i] = z;
            else if (i < 49152)  reinterpret_cast<float4*>(g_UV)[i - 32768] = z;
            else                 reinterpret_cast<float4*>(g_LV)[i - 49152] = z;
        }
    } else {
        // usr_vec: 32 blocks x 16 k each; 16 lanes per k
        int kblk = blk - 1152;
        int k    = kblk * 16 + (t >> 4);
        int lane = t & 15;
        float s = 0.f;
        #pragma unroll 8
        for (int h = lane; h < HH; h += 16)
            s += wih[(size_t)k * HH + h] * __ldg(&h0[h]);
        #pragma unroll
        for (int o = 8; o; o >>= 1) s += __shfl_down_sync(0xffffffffu, s, o, 16);
        if (lane == 0) g_usr[k] = s;
    }
}

// ---------------------------------------------------------------------------
// Masked gather-accumulate. Grid (64 b, 8 l-splits), block 512 (thread = h).
// acc = {ca,cb,da,db}-weighted sums of location rows; one float4 RED per thread.
__global__ void __launch_bounds__(512, 4) k_gather(
        const float* __restrict__ tdu, const float* __restrict__ tdl,
        const float* __restrict__ ldu, const float* __restrict__ ldl,
        const int*   __restrict__ cur, const int* __restrict__ llen,
        const float* __restrict__ locw) {
    int b = blockIdx.x;
    int split = blockIdx.y;                 // 0..7
    int len = llen[b];
    int h = threadIdx.x;

    __shared__ float4 s_cf[64];
    __shared__ int    s_idx[64];

    if (h < 64) {
        int l = split + 8 * h;
        if (l < len) {
            int o = b * LL + l;
            float tu = tdu[o], tl = tdl[o];
            float lu = ldu[o], ll = ldl[o];
            float tden = 1.f / (tu + tl + 1e-9f);
            float lden = 1.f / (lu + ll + 1e-9f);
            float a = tu * tden, bb_ = tl * tden;
            float c = lu * lden, dd  = ll * lden;
            s_cf[h] = make_float4(c * a, c * bb_, dd * a, dd * bb_);
            s_idx[h] = cur[o];
        }
    }
    __syncthreads();

    int cnt = (len > split) ? ((len - split + 7) >> 3) : 0;

    float4 acc = make_float4(0.f, 0.f, 0.f, 0.f);
    #pragma unroll 8
    for (int i = 0; i < cnt; ++i) {
        float v = __ldg(&locw[(size_t)s_idx[i] * HH + h]);
        float4 cf = s_cf[i];
        acc.x += cf.x * v;
        acc.y += cf.y * v;
        acc.z += cf.z * v;
        acc.w += cf.w * v;
    }
    if (cnt > 0)
        atomicAdd(reinterpret_cast<float4*>(&g_S[h][b][0]), acc);
}

// ---------------------------------------------------------------------------
// U[k][b] = sum_h Wtu[k][h]*S1[h][b] + Wtl[k][h]*S2[h][b]
// V[k][b] = sum_h Wtu[k][h]*S3[h][b] + Wtl[k][h]*S4[h][b]
// Grid (16 k-blocks of 32, 16 h-splits of 32). Block 256 = 8 warps;
// warp owns 4 k, lane owns 2 b. Vector RED epilogue into packed g_UV.
__global__ void __launch_bounds__(256) k_mm1() {
    int warp = threadIdx.x >> 5, lane = threadIdx.x & 31;
    int k0 = blockIdx.x * 32 + warp * 4;
    int h0 = blockIdx.y * 32;
    int b0 = 2 * lane;

    float aU[4][2] = {{0.f}}, aV[4][2] = {{0.f}};
    #pragma unroll 4
    for (int h = h0; h < h0 + 32; ++h) {
        float4 s0 = *reinterpret_cast<const float4*>(&g_S[h][b0][0]);     // {s1,s2,s3,s4} b0
        float4 s1 = *reinterpret_cast<const float4*>(&g_S[h][b0 + 1][0]); // b0+1
        float4 wu = *reinterpret_cast<const float4*>(&g_Wt[0][h][k0]);
        float4 wl = *reinterpret_cast<const float4*>(&g_Wt[1][h][k0]);
        float wuj[4] = {wu.x, wu.y, wu.z, wu.w};
        float wlj[4] = {wl.x, wl.y, wl.z, wl.w};
        #pragma unroll
        for (int j = 0; j < 4; ++j) {
            aU[j][0] += wuj[j] * s0.x + wlj[j] * s0.y;
            aU[j][1] += wuj[j] * s1.x + wlj[j] * s1.y;
            aV[j][0] += wuj[j] * s0.z + wlj[j] * s0.w;
            aV[j][1] += wuj[j] * s1.z + wlj[j] * s1.w;
        }
    }
    #pragma unroll
    for (int j = 0; j < 4; ++j) {
        // g_UV[k][b0][0..1], g_UV[k][b0+1][0..1] are 4 consecutive floats
        float4 v = make_float4(aU[j][0], aV[j][0], aU[j][1], aV[j][1]);
        atomicAdd(reinterpret_cast<float4*>(&g_UV[k0 + j][b0][0]), v);
    }
}

// ---------------------------------------------------------------------------
// loc_vec[b][k] = sum_h Wsu[k][h]*U[h][b] + Wsl[k][h]*V[h][b]
__global__ void __launch_bounds__(256) k_mm2() {
    int warp = threadIdx.x >> 5, lane = threadIdx.x & 31;
    int k0 = blockIdx.x * 32 + warp * 4;
    int h0 = blockIdx.y * 32;
    int b0 = 2 * lane;

    float acc[4][2] = {{0.f}};
    #pragma unroll 4
    for (int h = h0; h < h0 + 32; ++h) {
        float4 uv = *reinterpret_cast<const float4*>(&g_UV[h][b0][0]); // {U0,V0,U1,V1}
        float4 wu = *reinterpret_cast<const float4*>(&g_Wt[2][h][k0]);
        float4 wl = *reinterpret_cast<const float4*>(&g_Wt[3][h][k0]);
        float wuj[4] = {wu.x, wu.y, wu.z, wu.w};
        float wlj[4] = {wl.x, wl.y, wl.z, wl.w};
        #pragma unroll
        for (int j = 0; j < 4; ++j) {
            acc[j][0] += wuj[j] * uv.x + wlj[j] * uv.y;
            acc[j][1] += wuj[j] * uv.z + wlj[j] * uv.w;
        }
    }
    // g_LV[b][k0..k0+3] contiguous per b -> one float4 RED per b
    float4 r0 = make_float4(acc[0][0], acc[1][0], acc[2][0], acc[3][0]);
    float4 r1 = make_float4(acc[0][1], acc[1][1], acc[2][1], acc[3][1]);
    atomicAdd(reinterpret_cast<float4*>(&g_LV[b0][k0]), r0);
    atomicAdd(reinterpret_cast<float4*>(&g_LV[b0 + 1][k0]), r1);
}

// ---------------------------------------------------------------------------
// out[b][k] = softmax_k( loc_vec[b][k] + usr[k] )
__global__ void __launch_bounds__(256) k_softmax(float* __restrict__ out) {
    int b = blockIdx.x;
    int t = threadIdx.x;        // 256 threads, 2 elements each
    int warp = t >> 5, lane = t & 31;
    __shared__ float sm[8];
    __shared__ float sbc;

    float x0 = g_LV[b][t]       + g_usr[t];
    float x1 = g_LV[b][t + 256] + g_usr[t + 256];

    float m = fmaxf(x0, x1);
    #pragma unroll
    for (int o = 16; o; o >>= 1) m = fmaxf(m, __shfl_xor_sync(0xffffffffu, m, o));
    if (lane == 0) sm[warp] = m;
    __syncthreads();
    if (t == 0) {
        float M = sm[0];
        #pragma unroll
        for (int i = 1; i < 8; ++i) M = fmaxf(M, sm[i]);
        sbc = M;
    }
    __syncthreads();
    float M = sbc;

    float e0 = expf(x0 - M), e1 = expf(x1 - M);
    float s = e0 + e1;
    #pragma unroll
    for (int o = 16; o; o >>= 1) s += __shfl_xor_sync(0xffffffffu, s, o);
    __syncthreads();           // all reads of sbc(M) done before reuse
    if (lane == 0) sm[warp] = s;
    __syncthreads();
    if (t == 0) {
        float S = 0.f;
        #pragma unroll
        for (int i = 0; i < 8; ++i) S += sm[i];
        sbc = S;
    }
    __syncthreads();
    float inv = 1.f / sbc;
    out[b * HH + t]       = e0 * inv;
    out[b * HH + t + 256] = e1 * inv;
}

// ---------------------------------------------------------------------------
extern "C" void kernel_launch(void* const* d_in, const int* in_sizes, int n_in,
                              void* d_out, int out_size) {
    const float* tdu  = (const float*)d_in[0];
    const float* tdl  = (const float*)d_in[1];
    const float* ldu  = (const float*)d_in[2];
    const float* ldl  = (const float*)d_in[3];
    const int*   cur  = (const int*)  d_in[4];
    const int*   llen = (const int*)  d_in[5];
    const float* wih  = (const float*)d_in[6];
    const float* wtu  = (const float*)d_in[7];
    const float* wtl  = (const float*)d_in[8];
    const float* wsu  = (const float*)d_in[9];
    const float* wsl  = (const float*)d_in[10];
    const float* h0   = (const float*)d_in[11];
    const float* locw = (const float*)d_in[12];
    float* out = (float*)d_out;

    k_pre<<<1184, 256>>>(wtu, wtl, wsu, wsl, wih, h0);
    k_gather<<<dim3(64, 8), 512>>>(tdu, tdl, ldu, ldl, cur, llen, locw);
    k_mm1<<<dim3(16, 16), 256>>>();
    k_mm2<<<dim3(16, 16), 256>>>();
    k_softmax<<<64, 256>>>(out);
}

// round 3
// speedup vs baseline: 1.8193x; 1.1063x over previous
#include <cuda_runtime.h>

#define BB 64
#define LL 512
#define HH 512
#define NBLK 148

// Scratch (device globals — no allocation allowed)
__device__ __align__(16) float g_S[HH][BB][4];   // packed {ca,cb,da,db}-weighted sums
__device__ __align__(16) float g_UV[HH][BB][2];  // packed {U,V}
__device__ __align__(16) float g_LV[BB][HH];
__device__ __align__(16) float g_usr[HH];
__device__ unsigned g_bar_cnt;
__device__ unsigned g_bar_gen;

// Grid-wide barrier: all NBLK blocks resident (1/SM), release/acquire via L2 atomics.
__device__ __forceinline__ void grid_sync() {
    __syncthreads();
    if (threadIdx.x == 0) {
        __threadfence();                                   // release
        unsigned gen = atomicAdd(&g_bar_gen, 0u);
        if (atomicAdd(&g_bar_cnt, 1u) == NBLK - 1u) {
            g_bar_cnt = 0u;
            __threadfence();
            atomicAdd(&g_bar_gen, 1u);
        } else {
            while (atomicAdd(&g_bar_gen, 0u) == gen) __nanosleep(64);
        }
        __threadfence();                                   // acquire
    }
    __syncthreads();
}

__global__ void __launch_bounds__(1024, 1) k_fused(
        const float* __restrict__ tdu, const float* __restrict__ tdl,
        const float* __restrict__ ldu, const float* __restrict__ ldl,
        const int*   __restrict__ cur, const int* __restrict__ llen,
        const float* __restrict__ wih, const float* __restrict__ wtu,
        const float* __restrict__ wtl, const float* __restrict__ wsu,
        const float* __restrict__ wsl, const float* __restrict__ h0,
        const float* __restrict__ locw, float* __restrict__ out) {
    __shared__ __align__(16) unsigned char smem_raw[49152];
    const int B = blockIdx.x;
    const int t = threadIdx.x;

    // ---------------- P0: zero scratch + usr_vec ----------------
    {
        int idx = B * 1024 + t;
        float4 z = make_float4(0.f, 0.f, 0.f, 0.f);
        if (idx < 32768)       reinterpret_cast<float4*>(g_S)[idx] = z;
        else if (idx < 49152)  reinterpret_cast<float4*>(g_UV)[idx - 32768] = z;
        else if (idx < 57344)  reinterpret_cast<float4*>(g_LV)[idx - 49152] = z;
        if (B >= 140) {   // usr_vec = Wih @ h0 : 8 blocks x 64 k, 16 lanes/k
            int k    = (B - 140) * 64 + (t >> 4);
            int lane = t & 15;
            float s = 0.f;
            #pragma unroll 8
            for (int h = lane; h < HH; h += 16)
                s += wih[(size_t)k * HH + h] * __ldg(&h0[h]);
            #pragma unroll
            for (int o = 8; o; o >>= 1) s += __shfl_down_sync(0xffffffffu, s, o, 16);
            if (lane == 0) g_usr[k] = s;
        }
    }
    grid_sync();

    // ---------------- P1: masked gather-accumulate ----------------
    {
        float4* s_cf  = reinterpret_cast<float4*>(smem_raw);           // [2][64]
        int*    s_idx = reinterpret_cast<int*>(smem_raw + 2048);       // [2][64]
        int which = t >> 9;            // two units in flight per block
        int h = t & 511;
        for (int u0 = B * 2; u0 < 512; u0 += 2 * NBLK) {
            int u = u0 + which;
            int b = u >> 3, split = u & 7;
            int len = llen[b];
            if (h < 64) {
                int l = split + 8 * h;
                if (l < len) {
                    int o = b * LL + l;
                    float tu = tdu[o], tl = tdl[o];
                    float lu = ldu[o], ll = ldl[o];
                    float tden = 1.f / (tu + tl + 1e-9f);
                    float lden = 1.f / (lu + ll + 1e-9f);
                    float a = tu * tden, bb_ = tl * tden;
                    float c = lu * lden, dd  = ll * lden;
                    s_cf[which * 64 + h]  = make_float4(c * a, c * bb_, dd * a, dd * bb_);
                    s_idx[which * 64 + h] = cur[o];
                }
            }
            __syncthreads();
            int cnt = (len > split) ? ((len - split + 7) >> 3) : 0;
            const float4* cf = s_cf + which * 64;
            const int*    ix = s_idx + which * 64;
            float4 acc = make_float4(0.f, 0.f, 0.f, 0.f);
            #pragma unroll 8
            for (int i = 0; i < cnt; ++i) {
                float v = __ldg(&locw[(size_t)ix[i] * HH + h]);
                float4 c4 = cf[i];
                acc.x += c4.x * v; acc.y += c4.y * v;
                acc.z += c4.z * v; acc.w += c4.w * v;
            }
            if (cnt > 0)
                atomicAdd(reinterpret_cast<float4*>(&g_S[h][b][0]), acc);
            __syncthreads();
        }
    }
    grid_sync();

    // ---------------- P2: mm1  U/V[k][b] = sum_h Wt{u,l}[k][h] * S{..}[h][b] --
    if (B < 128) {
        int kblk = B >> 4, hsplit = B & 15;      // 8 kblks x 64k, 16 hsplits x 32h
        int k0 = kblk * 64, hb = hsplit * 32;
        float4* ss4 = reinterpret_cast<float4*>(smem_raw);          // [32][64]
        float*  swt = reinterpret_cast<float*>(smem_raw + 32768);   // [2][64][32]
        #pragma unroll
        for (int i = t; i < 2048; i += 1024) {
            int h = i >> 6, b = i & 63;
            ss4[i] = __ldcg(reinterpret_cast<const float4*>(&g_S[hb + h][b][0]));
        }
        {
            int m = t >> 9;                 // mat
            int r = (t >> 3) & 63;          // k row
            int i4 = t & 7;                 // float4 within 32 h
            const float* W = m ? wtl : wtu;
            float4 v = __ldg(reinterpret_cast<const float4*>(&W[(size_t)(k0 + r) * HH + hb + i4 * 4]));
            *reinterpret_cast<float4*>(&swt[(m * 64 + r) * 32 + i4 * 4]) = v;
        }
        __syncthreads();
        int w = t >> 5, lane = t & 31;
        int kg = w & 15, hs = w >> 4;       // 16 kgroups x 4k, 2 hsubs x 16h
        int kb = kg * 4;
        float aU[4][2] = {{0.f}}, aV[4][2] = {{0.f}};
        for (int hh = 0; hh < 16; ++hh) {
            int h = hs * 16 + hh;
            float4 a = ss4[h * 64 + lane];
            float4 c = ss4[h * 64 + lane + 32];
            #pragma unroll
            for (int j = 0; j < 4; ++j) {
                float wu = swt[(kb + j) * 32 + h];
                float wl = swt[(64 + kb + j) * 32 + h];
                aU[j][0] += wu * a.x + wl * a.y;
                aV[j][0] += wu * a.z + wl * a.w;
                aU[j][1] += wu * c.x + wl * c.y;
                aV[j][1] += wu * c.z + wl * c.w;
            }
        }
        __syncthreads();
        float2* uvacc = reinterpret_cast<float2*>(smem_raw);        // [64][64], overlays ss4
        #pragma unroll
        for (int p = 0; p < 2; ++p) {
            if (hs == p) {
                #pragma unroll
                for (int j = 0; j < 4; ++j) {
                    int r0 = (kb + j) * 64 + lane;
                    if (p == 0) {
                        uvacc[r0]      = make_float2(aU[j][0], aV[j][0]);
                        uvacc[r0 + 32] = make_float2(aU[j][1], aV[j][1]);
                    } else {
                        float2 x = uvacc[r0];
                        x.x += aU[j][0]; x.y += aV[j][0]; uvacc[r0] = x;
                        float2 y = uvacc[r0 + 32];
                        y.x += aU[j][1]; y.y += aV[j][1]; uvacc[r0 + 32] = y;
                    }
                }
            }
            __syncthreads();
        }
        float4* dst = reinterpret_cast<float4*>(&g_UV[k0][0][0]);   // 2048 float4
        const float4* src = reinterpret_cast<const float4*>(smem_raw);
        atomicAdd(&dst[t],        src[t]);
        atomicAdd(&dst[t + 1024], src[t + 1024]);
    }
    grid_sync();

    // ---------------- P3: mm2  LV[b][k] = sum_h Ws{u,l}[k][h] * {U,V}[h][b] --
    if (B < 128) {
        int kblk = B >> 3, hsplit = B & 7;       // 16 kblks x 32k, 8 hsplits x 64h
        int k0 = kblk * 32, hb = hsplit * 64;
        float2* suv = reinterpret_cast<float2*>(smem_raw);          // [64][64]
        float*  swt = reinterpret_cast<float*>(smem_raw + 32768);   // [2][32][64]
        #pragma unroll
        for (int i = t; i < 2048; i += 1024)
            reinterpret_cast<float4*>(suv)[i] =
                __ldcg(&reinterpret_cast<const float4*>(g_UV)[hb * 32 + i]);
        {
            int m = t >> 9;
            int r = (t >> 4) & 31;
            int i4 = t & 15;
            const float* W = m ? wsl : wsu;
            float4 v = __ldg(reinterpret_cast<const float4*>(&W[(size_t)(k0 + r) * HH + hb + i4 * 4]));
            *reinterpret_cast<float4*>(&swt[(m * 32 + r) * 64 + i4 * 4]) = v;
        }
        __syncthreads();
        int w = t >> 5, lane = t & 31;
        int kg = w & 7, hs = w >> 3;             // 8 kgroups x 4k, 4 hsubs x 16h
        int kb = kg * 4;
        float acc[4][2] = {{0.f}};
        for (int hh = 0; hh < 16; ++hh) {
            int h = hs * 16 + hh;
            float2 a = suv[h * 64 + lane];
            float2 c = suv[h * 64 + lane + 32];
            #pragma unroll
            for (int j = 0; j < 4; ++j) {
                float wu = swt[(kb + j) * 64 + h];
                float wl = swt[(32 + kb + j) * 64 + h];
                acc[j][0] += wu * a.x + wl * a.y;
                acc[j][1] += wu * c.x + wl * c.y;
            }
        }
        __syncthreads();
        float* lv = reinterpret_cast<float*>(smem_raw + 32768);     // [32][64], overlays swt
        #pragma unroll
        for (int p = 0; p < 4; ++p) {
            if (hs == p) {
                #pragma unroll
                for (int j = 0; j < 4; ++j) {
                    int r0 = (kb + j) * 64 + lane;
                    if (p == 0) { lv[r0] = acc[j][0]; lv[r0 + 32] = acc[j][1]; }
                    else        { lv[r0] += acc[j][0]; lv[r0 + 32] += acc[j][1]; }
                }
            }
            __syncthreads();
        }
        int b = t & 63, k = (t >> 6) * 2;
        float2 v = make_float2(lv[k * 64 + b], lv[(k + 1) * 64 + b]);
        atomicAdd(reinterpret_cast<float2*>(&g_LV[b][k0 + k]), v);
    }
    grid_sync();

    // ---------------- P4: softmax ----------------
    if (B < 64) {
        float* red = reinterpret_cast<float*>(smem_raw);
        int warp = t >> 5, lane = t & 31;
        float x = -1e30f;
        if (t < 512) x = __ldcg(&g_LV[B][t]) + __ldcg(&g_usr[t]);
        float m = x;
        #pragma unroll
        for (int o = 16; o; o >>= 1) m = fmaxf(m, __shfl_xor_sync(0xffffffffu, m, o));
        if (lane == 0) red[warp] = m;
        __syncthreads();
        if (t == 0) {
            float M = red[0];
            #pragma unroll
            for (int i = 1; i < 32; ++i) M = fmaxf(M, red[i]);
            red[32] = M;
        }
        __syncthreads();
        float M = red[32];
        float e = (t < 512) ? expf(x - M) : 0.f;
        float s = e;
        #pragma unroll
        for (int o = 16; o; o >>= 1) s += __shfl_xor_sync(0xffffffffu, s, o);
        __syncthreads();
        if (lane == 0) red[warp] = s;
        __syncthreads();
        if (t == 0) {
            float S = 0.f;
            #pragma unroll
            for (int i = 0; i < 32; ++i) S += red[i];
            red[33] = S;
        }
        __syncthreads();
        if (t < 512) out[B * HH + t] = e * (1.f / red[33]);
    }
}

// ---------------------------------------------------------------------------
extern "C" void kernel_launch(void* const* d_in, const int* in_sizes, int n_in,
                              void* d_out, int out_size) {
    const float* tdu  = (const float*)d_in[0];
    const float* tdl  = (const float*)d_in[1];
    const float* ldu  = (const float*)d_in[2];
    const float* ldl  = (const float*)d_in[3];
    const int*   cur  = (const int*)  d_in[4];
    const int*   llen = (const int*)  d_in[5];
    const float* wih  = (const float*)d_in[6];
    const float* wtu  = (const float*)d_in[7];
    const float* wtl  = (const float*)d_in[8];
    const float* wsu  = (const float*)d_in[9];
    const float* wsl  = (const float*)d_in[10];
    const float* h0   = (const float*)d_in[11];
    const float* locw = (const float*)d_in[12];
    float* out = (float*)d_out;

    k_fused<<<NBLK, 1024>>>(tdu, tdl, ldu, ldl, cur, llen,
                            wih, wtu, wtl, wsu, wsl, h0, locw, out);
}

// round 5
// speedup vs baseline: 2.0443x; 1.1236x over previous
#include <cuda_runtime.h>

#define BB 64
#define LL 512
#define HH 512
#define NBLK 148

typedef unsigned long long ull;

// Scratch (device globals, zero-initialized at module load; kernel maintains the
// "zero at exit" invariant for g_S/g_UV/g_LV so no zeroing phase is needed).
__device__ __align__(16) float g_S[HH][BB][4];   // packed {ca,cb,da,db}-weighted sums
__device__ __align__(16) float g_UV[HH][BB][2];  // packed {U,V}
__device__ __align__(16) float g_LV[BB][HH];
__device__ __align__(16) float g_usr[HH];

// two-level barrier state
__device__ unsigned g_cnt1[320];          // 10 groups, 128B apart
__device__ unsigned g_cnt2;
__device__ volatile unsigned g_gen;

__device__ __forceinline__ void grid_sync() {
    __syncthreads();
    if (threadIdx.x == 0) {
        unsigned gen = g_gen;
        __threadfence();                                  // release
        unsigned g = blockIdx.x >> 4;                     // 10 groups (last has 4)
        unsigned gs = (g == 9u) ? 4u : 16u;
        if (atomicAdd(&g_cnt1[g * 32], 1u) == gs - 1u) {
            g_cnt1[g * 32] = 0u;
            __threadfence();
            if (atomicAdd(&g_cnt2, 1u) == 9u) {
                g_cnt2 = 0u;
                __threadfence();
                g_gen = gen + 1u;
            } else {
                while (g_gen == gen) {}
            }
        } else {
            while (g_gen == gen) {}
        }
        __threadfence();                                  // acquire
    }
    __syncthreads();
}

// ---- packed fp32x2 helpers -------------------------------------------------
__device__ __forceinline__ ull pack2(float x, float y) {
    ull r; asm("mov.b64 %0, {%1, %2};" : "=l"(r) : "f"(x), "f"(y)); return r;
}
__device__ __forceinline__ ull bcast2(float x) { return pack2(x, x); }
__device__ __forceinline__ float2 unpack2(ull v) {
    float2 r; asm("mov.b64 {%0, %1}, %2;" : "=f"(r.x), "=f"(r.y) : "l"(v)); return r;
}
__device__ __forceinline__ void ffma2(ull& d, ull a, ull b) {
    asm("fma.rn.f32x2 %0, %1, %2, %0;" : "+l"(d) : "l"(a), "l"(b));
}

__global__ void __launch_bounds__(1024, 1) k_fused(
        const float* __restrict__ tdu, const float* __restrict__ tdl,
        const float* __restrict__ ldu, const float* __restrict__ ldl,
        const int*   __restrict__ cur, const int* __restrict__ llen,
        const float* __restrict__ wih, const float* __restrict__ wtu,
        const float* __restrict__ wtl, const float* __restrict__ wsu,
        const float* __restrict__ wsl, const float* __restrict__ h0,
        const float* __restrict__ locw, float* __restrict__ out) {
    __shared__ __align__(16) unsigned char smem_raw[49152];
    const int B = blockIdx.x;
    const int t = threadIdx.x;

    // ============= P1: gather-accumulate (+ usr_vec on blocks 140..147) =====
    {
        float4* s_cf  = reinterpret_cast<float4*>(smem_raw);            // [4][64]
        int*    s_idx = reinterpret_cast<int*>(smem_raw + 4096);        // [4][64]
        float4* sbufA = reinterpret_cast<float4*>(smem_raw + 5120);     // [512]
        float4* sbufB = reinterpret_cast<float4*>(smem_raw + 13312);    // [512]

        int nu = (B < 68) ? 4 : 3;       // units u = B + i*NBLK < 512

        if (B >= 140) {   // usr_vec = Wih @ h0 : 8 blocks x 64 k, 16 lanes/k
            int k    = (B - 140) * 64 + (t >> 4);
            int lane = t & 15;
            float s = 0.f;
            #pragma unroll 8
            for (int h = lane; h < HH; h += 16)
                s += wih[(size_t)k * HH + h] * __ldg(&h0[h]);
            #pragma unroll
            for (int o = 8; o; o >>= 1) s += __shfl_down_sync(0xffffffffu, s, o, 16);
            if (lane == 0) g_usr[k] = s;
        }

        // preload all units' per-row coefficients
        if (t < nu * 64) {
            int i = t >> 6, r = t & 63;
            int u = B + i * NBLK;
            int b = u >> 3, sp = u & 7;
            int len = __ldg(&llen[b]);
            int l = sp + 8 * r;
            if (l < len) {
                int o = b * LL + l;
                float tu = tdu[o], tl = tdl[o];
                float lu = ldu[o], ll = ldl[o];
                float tden = 1.f / (tu + tl + 1e-9f);
                float lden = 1.f / (lu + ll + 1e-9f);
                float a = tu * tden, bb_ = tl * tden;
                float c = lu * lden, dd  = ll * lden;
                s_cf[t]  = make_float4(c * a, c * bb_, dd * a, dd * bb_);
                s_idx[t] = cur[o];
            }
        }
        __syncthreads();

        int h2 = t & 255;          // float2 position: h = 2*h2, 2*h2+1
        int rg = t >> 8;           // 0..3 row groups
        for (int i = 0; i < nu; ++i) {
            int u = B + i * NBLK;
            int b = u >> 3, sp = u & 7;
            int len = __ldg(&llen[b]);
            int cnt = (len > sp) ? ((len - sp + 7) >> 3) : 0;

            ull a1 = 0, a2 = 0, a3 = 0, a4 = 0;     // packed (h_even, h_odd)
            #pragma unroll 4
            for (int r = rg; r < cnt; r += 4) {
                ull v = __ldg(reinterpret_cast<const ull*>(
                            &locw[(size_t)s_idx[i * 64 + r] * HH + 2 * h2]));
                float4 cf = s_cf[i * 64 + r];
                ffma2(a1, bcast2(cf.x), v);
                ffma2(a2, bcast2(cf.y), v);
                ffma2(a3, bcast2(cf.z), v);
                ffma2(a4, bcast2(cf.w), v);
            }
            float2 u1 = unpack2(a1), u2 = unpack2(a2), u3 = unpack2(a3), u4 = unpack2(a4);
            float4 ev = make_float4(u1.x, u2.x, u3.x, u4.x);   // h even
            float4 od = make_float4(u1.y, u2.y, u3.y, u4.y);   // h odd

            __syncthreads();   // sbuf free (prev unit's REDs done)
            if (rg == 0) { sbufA[2 * h2] = ev; sbufA[2 * h2 + 1] = od; }
            if (rg == 1) { sbufB[2 * h2] = ev; sbufB[2 * h2 + 1] = od; }
            __syncthreads();
            if (rg == 2) {
                float4 x = sbufA[2 * h2];
                x.x += ev.x; x.y += ev.y; x.z += ev.z; x.w += ev.w; sbufA[2 * h2] = x;
                float4 y = sbufA[2 * h2 + 1];
                y.x += od.x; y.y += od.y; y.z += od.z; y.w += od.w; sbufA[2 * h2 + 1] = y;
            }
            if (rg == 3) {
                float4 x = sbufB[2 * h2];
                x.x += ev.x; x.y += ev.y; x.z += ev.z; x.w += ev.w; sbufB[2 * h2] = x;
                float4 y = sbufB[2 * h2 + 1];
                y.x += od.x; y.y += od.y; y.z += od.z; y.w += od.w; sbufB[2 * h2 + 1] = y;
            }
            __syncthreads();
            if (t < 512 && cnt > 0) {
                float4 x = sbufA[t], y = sbufB[t];
                x.x += y.x; x.y += y.y; x.z += y.z; x.w += y.w;
                atomicAdd(reinterpret_cast<float4*>(&g_S[t][b][0]), x);
            }
        }
    }
    grid_sync();

    // ============= P2: mm1  U/V[k][b] = sum_h Wt{u,l}[k][h] * S[h][b] =======
    if (B < 128) {
        int kblk = B >> 4, hsplit = B & 15;        // 8 kblk x 64k, 16 hsplit x 32h
        int k0 = kblk * 64, hb = hsplit * 32;
        float* s_t = reinterpret_cast<float*>(smem_raw);           // [32h][4s][64b]
        float* swt = reinterpret_cast<float*>(smem_raw + 32768);   // [2m][64k][32h]
        #pragma unroll
        for (int i = t; i < 2048; i += 1024) {
            int h = i >> 6, b = i & 63;
            float4 v = *reinterpret_cast<const float4*>(&g_S[hb + h][b][0]);
            float* p = &s_t[h * 256 + b];
            p[0] = v.x; p[64] = v.y; p[128] = v.z; p[192] = v.w;
        }
        {
            int m = t >> 9, r = (t >> 3) & 63, i4 = t & 7;
            const float* W = m ? wtl : wtu;
            float4 v = __ldg(reinterpret_cast<const float4*>(
                           &W[(size_t)(k0 + r) * HH + hb + i4 * 4]));
            *reinterpret_cast<float4*>(&swt[(m * 64 + r) * 32 + i4 * 4]) = v;
        }
        __syncthreads();
        int w = t >> 5, lane = t & 31;
        int kg = w & 15, hs = w >> 4;              // 16 kgroups x 4k, 2 hsubs x 16h
        int kb = kg * 4;
        ull aU[4] = {0, 0, 0, 0}, aV[4] = {0, 0, 0, 0};   // packed (b0, b0+1)
        for (int hh = 0; hh < 16; ++hh) {
            int h = hs * 16 + hh;
            const float* row = &s_t[h * 256];
            ull s1 = *reinterpret_cast<const ull*>(&row[2 * lane]);
            ull s2 = *reinterpret_cast<const ull*>(&row[64 + 2 * lane]);
            ull s3 = *reinterpret_cast<const ull*>(&row[128 + 2 * lane]);
            ull s4 = *reinterpret_cast<const ull*>(&row[192 + 2 * lane]);
            #pragma unroll
            for (int j = 0; j < 4; ++j) {
                ull wu = bcast2(swt[(kb + j) * 32 + h]);
                ull wl = bcast2(swt[(64 + kb + j) * 32 + h]);
                ffma2(aU[j], wu, s1); ffma2(aU[j], wl, s2);
                ffma2(aV[j], wu, s3); ffma2(aV[j], wl, s4);
            }
        }
        __syncthreads();
        float4* ub = reinterpret_cast<float4*>(smem_raw);   // [64k][32 pairs]
        #pragma unroll
        for (int p = 0; p < 2; ++p) {
            if (hs == p) {
                #pragma unroll
                for (int j = 0; j < 4; ++j) {
                    float2 u = unpack2(aU[j]), v = unpack2(aV[j]);
                    int idx = (kb + j) * 32 + lane;
                    if (p == 0) ub[idx] = make_float4(u.x, v.x, u.y, v.y);
                    else {
                        float4 x = ub[idx];
                        x.x += u.x; x.y += v.x; x.z += u.y; x.w += v.y;
                        ub[idx] = x;
                    }
                }
            }
            __syncthreads();
        }
        float4* dst = reinterpret_cast<float4*>(&g_UV[k0][0][0]);
        atomicAdd(&dst[t],        ub[t]);
        atomicAdd(&dst[t + 1024], ub[t + 1024]);
    }
    grid_sync();

    // ============= P3: mm2  LV[b][k] = sum_h Ws{u,l}[k][h]*{U,V}[h][b] ======
    if (B < 128) {
        int kblk = B >> 3, hsplit = B & 7;         // 16 kblk x 32k, 8 hsplit x 64h
        int k0 = kblk * 32, hb = hsplit * 64;
        ull*   uP  = reinterpret_cast<ull*>(smem_raw);             // [64h][32bp]
        ull*   vP  = reinterpret_cast<ull*>(smem_raw + 16384);     // [64h][32bp]
        float* swt = reinterpret_cast<float*>(smem_raw + 32768);   // [2m][32k][64h]
        #pragma unroll
        for (int i = t; i < 2048; i += 1024) {
            int h = i >> 5, bp = i & 31;
            float4 q = *reinterpret_cast<const float4*>(&g_UV[hb + h][bp * 2][0]);
            uP[h * 32 + bp] = pack2(q.x, q.z);     // (U_b0, U_b1)
            vP[h * 32 + bp] = pack2(q.y, q.w);     // (V_b0, V_b1)
        }
        {
            int m = t >> 9, r = (t >> 4) & 31, i4 = t & 15;
            const float* W = m ? wsl : wsu;
            float4 v = __ldg(reinterpret_cast<const float4*>(
                           &W[(size_t)(k0 + r) * HH + hb + i4 * 4]));
            *reinterpret_cast<float4*>(&swt[(m * 32 + r) * 64 + i4 * 4]) = v;
        }
        __syncthreads();
        int w = t >> 5, lane = t & 31;
        int kg = w & 7, hs = w >> 3;               // 8 kgroups x 4k, 4 hsubs x 16h
        int kb = kg * 4;
        ull acc[4] = {0, 0, 0, 0};                 // packed (b0, b0+1)
        for (int hh = 0; hh < 16; ++hh) {
            int h = hs * 16 + hh;
            ull up = uP[h * 32 + lane];
            ull vp = vP[h * 32 + lane];
            #pragma unroll
            for (int j = 0; j < 4; ++j) {
                ull wu = bcast2(swt[(kb + j) * 64 + h]);
                ull wl = bcast2(swt[(32 + kb + j) * 64 + h]);
                ffma2(acc[j], wu, up); ffma2(acc[j], wl, vp);
            }
        }
        __syncthreads();
        float* lv = reinterpret_cast<float*>(smem_raw);   // [32k][64b]
        #pragma unroll
        for (int p = 0; p < 4; ++p) {
            if (hs == p) {
                #pragma unroll
                for (int j = 0; j < 4; ++j) {
                    float2 u = unpack2(acc[j]);
                    int r0 = (kb + j) * 64 + 2 * lane;
                    if (p == 0) { lv[r0] = u.x; lv[r0 + 1] = u.y; }
                    else        { lv[r0] += u.x; lv[r0 + 1] += u.y; }
                }
            }
            __syncthreads();
        }
        int b = t & 63, k = (t >> 6) * 2;
        float2 v = make_float2(lv[k * 64 + b], lv[(k + 1) * 64 + b]);
        atomicAdd(reinterpret_cast<float2*>(&g_LV[b][k0 + k]), v);
    } else {
        // idle blocks restore the g_S == 0 invariant for the next replay
        float4 z = make_float4(0.f, 0.f, 0.f, 0.f);
        for (int i = (B - 128) * 1024 + t; i < 32768; i += 20 * 1024)
            reinterpret_cast<float4*>(g_S)[i] = z;
    }
    grid_sync();

    // ============= P4: softmax (+ zero g_LV / g_UV for next replay) =========
    if (B < 64) {
        float* red = reinterpret_cast<float*>(smem_raw);
        int warp = t >> 5, lane = t & 31;
        float x = -1e30f;
        if (t < 512) {
            x = __ldcg(&g_LV[B][t]) + __ldcg(&g_usr[t]);
            g_LV[B][t] = 0.f;                      // restore invariant
        }
        float m = x;
        #pragma unroll
        for (int o = 16; o; o >>= 1) m = fmaxf(m, __shfl_xor_sync(0xffffffffu, m, o));
        if (lane == 0) red[warp] = m;
        __syncthreads();
        if (t == 0) {
            float M = red[0];
            #pragma unroll
            for (int i = 1; i < 32; ++i) M = fmaxf(M, red[i]);
            red[32] = M;
        }
        __syncthreads();
        float M = red[32];
        float e = (t < 512) ? expf(x - M) : 0.f;
        float s = e;
        #pragma unroll
        for (int o = 16; o; o >>= 1) s += __shfl_xor_sync(0xffffffffu, s, o);
        __syncthreads();
        if (lane == 0) red[warp] = s;
        __syncthreads();
        if (t == 0) {
            float S = 0.f;
            #pragma unroll
            for (int i = 0; i < 32; ++i) S += red[i];
            red[33] = S;
        }
        __syncthreads();
        if (t < 512) out[B * HH + t] = e * (1.f / red[33]);
    } else {
        // restore g_UV == 0 invariant
        int idx = (B - 64) * 1024 + t;
        if (idx < 16384)
            reinterpret_cast<float4*>(g_UV)[idx] = make_float4(0.f, 0.f, 0.f, 0.f);
    }
}

// ---------------------------------------------------------------------------
extern "C" void kernel_launch(void* const* d_in, const int* in_sizes, int n_in,
                              void* d_out, int out_size) {
    const float* tdu  = (const float*)d_in[0];
    const float* tdl  = (const float*)d_in[1];
    const float* ldu  = (const float*)d_in[2];
    const float* ldl  = (const float*)d_in[3];
    const int*   cur  = (const int*)  d_in[4];
    const int*   llen = (const int*)  d_in[5];
    const float* wih  = (const float*)d_in[6];
    const float* wtu  = (const float*)d_in[7];
    const float* wtl  = (const float*)d_in[8];
    const float* wsu  = (const float*)d_in[9];
    const float* wsl  = (const float*)d_in[10];
    const float* h0   = (const float*)d_in[11];
    const float* locw = (const float*)d_in[12];
    float* out = (float*)d_out;

    k_fused<<<NBLK, 1024>>>(tdu, tdl, ldu, ldl, cur, llen,
                            wih, wtu, wtl, wsu, wsl, h0, locw, out);
}